// round 3
// baseline (speedup 1.0000x reference)
#include <cuda_runtime.h>
#include <cstdint>

// Problem constants (shapes are fixed by the dataset).
static constexpr int cN = 300000;
static constexpr int cE = 1500000;
static constexpr int cG = 30000;

// Scratch (device globals — no allocation allowed).
__device__ float g_x0[(size_t)cN * 32];
__device__ float g_h1[(size_t)cN * 64];
__device__ float g_h2[(size_t)cN * 64];
__device__ float g_agg[(size_t)cN * 3 * 64];   // reused: [N][3][32] then [N][3][64]
__device__ int   g_cnt[(size_t)cN * 3];
__device__ float g_gsum[(size_t)cG * 64];
__device__ int   g_gcnt[cG];

// ---------------------------------------------------------------------------
// Per-(dst, relation) in-degree counts.
__global__ void count_kernel(const int* __restrict__ ei, const int* __restrict__ et,
                             int* __restrict__ cnt, int E) {
    int e = blockIdx.x * blockDim.x + threadIdx.x;
    if (e >= E) return;
    atomicAdd(&cnt[ei[E + e] * 3 + et[e]], 1);
}

// Node features: x0 = shape_emb[sid] + col_emb[cid] + pos_emb[pid]  (N x 32)
__global__ void features_kernel(const int* __restrict__ sid, const int* __restrict__ cid,
                                const int* __restrict__ pid,
                                const float* __restrict__ se, const float* __restrict__ ce,
                                const float* __restrict__ pe,
                                float* __restrict__ x0, int N) {
    int t = blockIdx.x * blockDim.x + threadIdx.x;
    int n = t >> 3, q = t & 7;
    if (n >= N) return;
    float4 a = ((const float4*)(se + (size_t)sid[n] * 32))[q];
    float4 b = ((const float4*)(ce + (size_t)cid[n] * 32))[q];
    float4 c = ((const float4*)(pe + (size_t)pid[n] * 32))[q];
    ((float4*)(x0 + (size_t)n * 32))[q] =
        make_float4(a.x + b.x + c.x, a.y + b.y + c.y, a.z + b.z + c.z, a.w + b.w + c.w);
}

// Edge aggregation: agg[dst][et][*] += x[src][*] / max(cnt[dst][et],1)
// D/4 lanes per edge, float4 granularity -> coalesced gathers + coalesced REDs.
template <int D>
__global__ void edge_agg_kernel(const float* __restrict__ xin,
                                const int* __restrict__ ei,
                                const int* __restrict__ et,
                                const int* __restrict__ cnt,
                                float* __restrict__ agg, int E) {
    constexpr int L = D / 4;
    int t = blockIdx.x * blockDim.x + threadIdx.x;
    int e = t / L, q = t % L;
    if (e >= E) return;
    int s = ei[e], d = ei[E + e], r = et[e];
    int slot = d * 3 + r;
    float w = __fdividef(1.0f, (float)max(cnt[slot], 1));
    float4 v = ((const float4*)(xin + (size_t)s * D))[q];
    float* o = agg + (size_t)slot * D + q * 4;
    atomicAdd(o + 0, v.x * w);
    atomicAdd(o + 1, v.y * w);
    atomicAdd(o + 2, v.z * w);
    atomicAdd(o + 3, v.w * w);
}

// Fused transform: out[n] = act( b + agg[n] (3D wide) @ vstack(W_r) + x[n] @ root )
// = one logical [N x 4D] @ [4D x 64] GEMM; weights + staged inputs in smem.
// Block = 256 threads = 16 groups of 16 lanes; group -> node, lane -> 4 outputs.
template <int D, bool RELU>
__global__ void transform_kernel(const float* __restrict__ agg,
                                 const float* __restrict__ xin,
                                 const float* __restrict__ W,     // [3*D][64]
                                 const float* __restrict__ root,  // [D][64]
                                 const float* __restrict__ bias,  // [64]
                                 float* __restrict__ out, int N) {
    constexpr int IN = 4 * D;
    extern __shared__ float smem[];
    float4* Ws = (float4*)smem;            // [IN*16] float4 : Ws[k*16+l] = W[k][4l..4l+3]
    float*  ins = smem + (size_t)IN * 64;  // [16][(IN+4)] staged inputs (pad kills conflicts)

    for (int i = threadIdx.x; i < IN * 16; i += blockDim.x) {
        int k = i >> 4, l = i & 15;
        const float* row = (k < 3 * D) ? (W + (size_t)k * 64) : (root + (size_t)(k - 3 * D) * 64);
        Ws[i] = ((const float4*)row)[l];
    }

    int group = threadIdx.x >> 4;
    int lane  = threadIdx.x & 15;
    float4 b4 = ((const float4*)bias)[lane];

    for (int tile = blockIdx.x * 16; tile < N; tile += gridDim.x * 16) {
        __syncthreads();  // also covers the initial weight load
        for (int i = threadIdx.x; i < 16 * (IN / 4); i += blockDim.x) {
            int nl = i / (IN / 4), kq = i % (IN / 4);
            size_t node = (size_t)(tile + nl);
            float4 v;
            if (kq < 3 * D / 4) v = ((const float4*)(agg + node * 3 * D))[kq];
            else                v = ((const float4*)(xin + node * D))[kq - 3 * D / 4];
            *(float4*)(ins + nl * (IN + 4) + kq * 4) = v;
        }
        __syncthreads();

        float4 acc = b4;
        const float* inrow = ins + group * (IN + 4);
#pragma unroll 16
        for (int k = 0; k < IN; k++) {
            float v = inrow[k];
            float4 w = Ws[k * 16 + lane];
            acc.x = fmaf(v, w.x, acc.x);
            acc.y = fmaf(v, w.y, acc.y);
            acc.z = fmaf(v, w.z, acc.z);
            acc.w = fmaf(v, w.w, acc.w);
        }
        if (RELU) {
            acc.x = fmaxf(acc.x, 0.f); acc.y = fmaxf(acc.y, 0.f);
            acc.z = fmaxf(acc.z, 0.f); acc.w = fmaxf(acc.w, 0.f);
        }
        int node = tile + group;
        if (node < N) ((float4*)(out + (size_t)node * 64))[lane] = acc;
    }
}

// Global mean pool (sum + count); 16 lanes per node.
__global__ void pool_kernel(const float* __restrict__ h, const int* __restrict__ batch,
                            float* __restrict__ gsum, int* __restrict__ gcnt, int N) {
    int t = blockIdx.x * blockDim.x + threadIdx.x;
    int n = t >> 4, q = t & 15;
    if (n >= N) return;
    int b = batch[n];
    float4 v = ((const float4*)(h + (size_t)n * 64))[q];
    float* o = gsum + (size_t)b * 64 + q * 4;
    atomicAdd(o + 0, v.x);
    atomicAdd(o + 1, v.y);
    atomicAdd(o + 2, v.z);
    atomicAdd(o + 3, v.w);
    if (q == 0) atomicAdd(&gcnt[b], 1);
}

// Final: out[g] = (gsum[g]/max(cnt,1)) @ lin_W + lin_b. One warp per graph.
__global__ void pool_final_kernel(const float* __restrict__ gsum, const int* __restrict__ gcnt,
                                  const float* __restrict__ lw, const float* __restrict__ lb,
                                  float* __restrict__ out, int G) {
    int t = blockIdx.x * blockDim.x + threadIdx.x;
    int g = t >> 5, lane = t & 31;
    if (g >= G) return;
    float2 v = ((const float2*)(gsum + (size_t)g * 64))[lane];
    int k0 = 2 * lane, k1 = 2 * lane + 1;
    float a0 = v.x * lw[k0 * 2 + 0] + v.y * lw[k1 * 2 + 0];
    float a1 = v.x * lw[k0 * 2 + 1] + v.y * lw[k1 * 2 + 1];
#pragma unroll
    for (int off = 16; off; off >>= 1) {
        a0 += __shfl_down_sync(0xffffffff, a0, off);
        a1 += __shfl_down_sync(0xffffffff, a1, off);
    }
    if (lane == 0) {
        float c = fmaxf((float)gcnt[g], 1.0f);
        out[g * 2 + 0] = a0 / c + lb[0];
        out[g * 2 + 1] = a1 / c + lb[1];
    }
}

// ---------------------------------------------------------------------------
extern "C" void kernel_launch(void* const* d_in, const int* in_sizes, int n_in,
                              void* d_out, int out_size) {
    const int*   sid   = (const int*)d_in[0];
    const int*   cid   = (const int*)d_in[1];
    const int*   pid   = (const int*)d_in[2];
    const int*   ei    = (const int*)d_in[3];   // [2, E]: row0 = src, row1 = dst
    const int*   et    = (const int*)d_in[4];
    const int*   batch = (const int*)d_in[5];
    // d_in[6] = num_graphs (scalar), unused
    const float* se = (const float*)d_in[7];
    const float* ce = (const float*)d_in[8];
    const float* pe = (const float*)d_in[9];
    const float* W1 = (const float*)d_in[10];
    const float* r1 = (const float*)d_in[11];
    const float* b1 = (const float*)d_in[12];
    const float* W2 = (const float*)d_in[13];
    const float* r2 = (const float*)d_in[14];
    const float* b2 = (const float*)d_in[15];
    const float* lw = (const float*)d_in[16];
    const float* lb = (const float*)d_in[17];
    float* out = (float*)d_out;

    const int N = in_sizes[0];
    const int E = in_sizes[4];
    const int G = out_size / 2;

    void *p_x0, *p_h1, *p_h2, *p_agg, *p_cnt, *p_gsum, *p_gcnt;
    cudaGetSymbolAddress(&p_x0, g_x0);
    cudaGetSymbolAddress(&p_h1, g_h1);
    cudaGetSymbolAddress(&p_h2, g_h2);
    cudaGetSymbolAddress(&p_agg, g_agg);
    cudaGetSymbolAddress(&p_cnt, g_cnt);
    cudaGetSymbolAddress(&p_gsum, g_gsum);
    cudaGetSymbolAddress(&p_gcnt, g_gcnt);

    // Layer-2 transform needs >48KB dynamic smem.
    cudaFuncSetAttribute(transform_kernel<64, true>,
                         cudaFuncAttributeMaxDynamicSharedMemorySize, 100 * 1024);

    cudaMemsetAsync(p_cnt, 0, (size_t)N * 3 * sizeof(int));
    cudaMemsetAsync(p_gsum, 0, (size_t)G * 64 * sizeof(float));
    cudaMemsetAsync(p_gcnt, 0, (size_t)G * sizeof(int));

    count_kernel<<<(E + 255) / 256, 256>>>(ei, et, (int*)p_cnt, E);
    features_kernel<<<(N * 8 + 255) / 256, 256>>>(sid, cid, pid, se, ce, pe, (float*)p_x0, N);

    // ---- Layer 1 (D = 32) ----
    cudaMemsetAsync(p_agg, 0, (size_t)N * 3 * 32 * sizeof(float));
    edge_agg_kernel<32><<<(E * 8 + 255) / 256, 256>>>(
        (const float*)p_x0, ei, et, (const int*)p_cnt, (float*)p_agg, E);
    {
        int smem1 = (128 * 64 + 16 * (128 + 4)) * (int)sizeof(float);  // 41216 B
        transform_kernel<32, true><<<592, 256, smem1>>>(
            (const float*)p_agg, (const float*)p_x0, W1, r1, b1, (float*)p_h1, N);
    }

    // ---- Layer 2 (D = 64) ----
    cudaMemsetAsync(p_agg, 0, (size_t)N * 3 * 64 * sizeof(float));
    edge_agg_kernel<64><<<(E * 16 + 255) / 256, 256>>>(
        (const float*)p_h1, ei, et, (const int*)p_cnt, (float*)p_agg, E);
    {
        int smem2 = (256 * 64 + 16 * (256 + 4)) * (int)sizeof(float);  // 82176 B
        transform_kernel<64, true><<<296, 256, smem2>>>(
            (const float*)p_agg, (const float*)p_h1, W2, r2, b2, (float*)p_h2, N);
    }

    // ---- Pool + head ----
    pool_kernel<<<(N * 16 + 255) / 256, 256>>>(
        (const float*)p_h2, batch, (float*)p_gsum, (int*)p_gcnt, N);
    pool_final_kernel<<<(G * 32 + 255) / 256, 256>>>(
        (const float*)p_gsum, (const int*)p_gcnt, lw, lb, out, G);
}

// round 5
// speedup vs baseline: 1.7324x; 1.7324x over previous
#include <cuda_runtime.h>
#include <cstdint>

// Problem constants (shapes are fixed by the dataset).
static constexpr int cN = 300000;
static constexpr int cE = 1500000;
static constexpr int cG = 30000;

// Scratch (device globals — no allocation allowed).
__device__ float g_x0[(size_t)cN * 32];
__device__ float g_h1[(size_t)cN * 64];
__device__ float g_h2[(size_t)cN * 64];
__device__ float g_agg[(size_t)cN * 3 * 64];   // reused: [N][3][32] then [N][3][64]
__device__ int   g_cnt[(size_t)cN * 3];
__device__ float g_inv[(size_t)cN * 3];
__device__ float g_gsum[(size_t)cG * 64];
__device__ int   g_gcnt[cG];

// ---------------------------------------------------------------------------
// Per-(dst, relation) in-degree counts.
__global__ void count_kernel(const int* __restrict__ ei, const int* __restrict__ et,
                             int* __restrict__ cnt, int E) {
    int e = blockIdx.x * blockDim.x + threadIdx.x;
    if (e >= E) return;
    atomicAdd(&cnt[ei[E + e] * 3 + et[e]], 1);
}

// inv[i] = 1 / max(cnt[i], 1)
__global__ void inv_kernel(const int* __restrict__ cnt, float* __restrict__ inv, int M) {
    int i = blockIdx.x * blockDim.x + threadIdx.x;
    if (i >= M) return;
    inv[i] = __fdividef(1.0f, (float)max(cnt[i], 1));
}

// Node features: x0 = shape_emb[sid] + col_emb[cid] + pos_emb[pid]  (N x 32)
__global__ void features_kernel(const int* __restrict__ sid, const int* __restrict__ cid,
                                const int* __restrict__ pid,
                                const float* __restrict__ se, const float* __restrict__ ce,
                                const float* __restrict__ pe,
                                float* __restrict__ x0, int N) {
    int t = blockIdx.x * blockDim.x + threadIdx.x;
    int n = t >> 3, q = t & 7;
    if (n >= N) return;
    float4 a = ((const float4*)(se + (size_t)sid[n] * 32))[q];
    float4 b = ((const float4*)(ce + (size_t)cid[n] * 32))[q];
    float4 c = ((const float4*)(pe + (size_t)pid[n] * 32))[q];
    ((float4*)(x0 + (size_t)n * 32))[q] =
        make_float4(a.x + b.x + c.x, a.y + b.y + c.y, a.z + b.z + c.z, a.w + b.w + c.w);
}

// Edge aggregation: agg[dst][et][*] += x[src][*] * inv[dst][et]
// D/4 lanes per edge; one vector RED (red.global.add.v4.f32) per lane.
template <int D>
__global__ void edge_agg_kernel(const float* __restrict__ xin,
                                const int* __restrict__ ei,
                                const int* __restrict__ et,
                                const float* __restrict__ inv,
                                float* __restrict__ agg, int E) {
    constexpr int L = D / 4;
    int t = blockIdx.x * blockDim.x + threadIdx.x;
    int e = t / L, q = t % L;
    if (e >= E) return;
    int s = ei[e], d = ei[E + e], r = et[e];
    int slot = d * 3 + r;
    float w = inv[slot];
    float4 v = ((const float4*)(xin + (size_t)s * D))[q];
    float* o = agg + (size_t)slot * D + q * 4;
    asm volatile("red.global.add.v4.f32 [%0], {%1, %2, %3, %4};"
                 :: "l"(o), "f"(v.x * w), "f"(v.y * w), "f"(v.z * w), "f"(v.w * w)
                 : "memory");
}

// Fused transform: out[n] = act( b + agg[n] (3D wide) @ vstack(W_r) + x[n] @ root )
// = one logical [N x 4D] @ [4D x 64] GEMM.
// Block = 256 threads; tile = 128 nodes. Thread = (group g: 8 nodes) x (lane: 4 outs).
// Per k: 1 LDS.128 weight + 8 broadcast scalar LDS -> 32 FMA  (FMA-pipe bound).
template <int D, bool RELU>
__global__ void transform_kernel(const float* __restrict__ agg,
                                 const float* __restrict__ xin,
                                 const float* __restrict__ W,     // [3*D][64]
                                 const float* __restrict__ root,  // [D][64]
                                 const float* __restrict__ bias,  // [64]
                                 float* __restrict__ out, int N) {
    constexpr int IN = 4 * D;          // 128 / 256
    constexpr int CH = 64;             // k-chunk staged per pass
    constexpr int NCH = IN / CH;       // 2 / 4
    constexpr int STRIDE = CH + 4;     // 68 floats per staged node row
    extern __shared__ float smem[];
    float4* Ws = (float4*)smem;             // [IN*16]: Ws[k*16+l] = W[k][4l..4l+3]
    float*  ins = smem + (size_t)IN * 64;   // [128][STRIDE]

    for (int i = threadIdx.x; i < IN * 16; i += blockDim.x) {
        int k = i >> 4, l = i & 15;
        const float* row = (k < 3 * D) ? (W + (size_t)k * 64) : (root + (size_t)(k - 3 * D) * 64);
        Ws[i] = ((const float4*)row)[l];
    }

    int lane = threadIdx.x & 15;   // output quad
    int g    = threadIdx.x >> 4;   // node group (8 nodes)
    float4 b4 = ((const float4*)bias)[lane];

    for (int tile = blockIdx.x * 128; tile < N; tile += gridDim.x * 128) {
        float4 acc[8];
#pragma unroll
        for (int j = 0; j < 8; j++) acc[j] = b4;

#pragma unroll
        for (int c = 0; c < NCH; c++) {
            __syncthreads();   // also covers initial weight load / previous chunk reads
            for (int i = threadIdx.x; i < 128 * 16; i += blockDim.x) {
                int ni = i >> 4, kq = c * 16 + (i & 15);
                int node = tile + ni;
                float4 v = make_float4(0.f, 0.f, 0.f, 0.f);
                if (node < N) {
                    if (kq < 3 * D / 4) v = ((const float4*)(agg + (size_t)node * 3 * D))[kq];
                    else                v = ((const float4*)(xin + (size_t)node * D))[kq - 3 * D / 4];
                }
                *(float4*)(ins + (size_t)ni * STRIDE + (i & 15) * 4) = v;
            }
            __syncthreads();

            const float* base = ins + (size_t)g * 8 * STRIDE;
#pragma unroll 16
            for (int k = 0; k < CH; k++) {
                float4 w = Ws[(c * CH + k) * 16 + lane];
#pragma unroll
                for (int j = 0; j < 8; j++) {
                    float v = base[j * STRIDE + k];
                    acc[j].x = fmaf(v, w.x, acc[j].x);
                    acc[j].y = fmaf(v, w.y, acc[j].y);
                    acc[j].z = fmaf(v, w.z, acc[j].z);
                    acc[j].w = fmaf(v, w.w, acc[j].w);
                }
            }
        }

#pragma unroll
        for (int j = 0; j < 8; j++) {
            int node = tile + g * 8 + j;
            if (node < N) {
                float4 o = acc[j];
                if (RELU) {
                    o.x = fmaxf(o.x, 0.f); o.y = fmaxf(o.y, 0.f);
                    o.z = fmaxf(o.z, 0.f); o.w = fmaxf(o.w, 0.f);
                }
                ((float4*)(out + (size_t)node * 64))[lane] = o;
            }
        }
    }
}

// Global mean pool (sum + count); 16 lanes per node, vector RED.
__global__ void pool_kernel(const float* __restrict__ h, const int* __restrict__ batch,
                            float* __restrict__ gsum, int* __restrict__ gcnt, int N) {
    int t = blockIdx.x * blockDim.x + threadIdx.x;
    int n = t >> 4, q = t & 15;
    if (n >= N) return;
    int b = batch[n];
    float4 v = ((const float4*)(h + (size_t)n * 64))[q];
    float* o = gsum + (size_t)b * 64 + q * 4;
    asm volatile("red.global.add.v4.f32 [%0], {%1, %2, %3, %4};"
                 :: "l"(o), "f"(v.x), "f"(v.y), "f"(v.z), "f"(v.w)
                 : "memory");
    if (q == 0) atomicAdd(&gcnt[b], 1);
}

// Final: out[g] = (gsum[g]/max(cnt,1)) @ lin_W + lin_b. One warp per graph.
__global__ void pool_final_kernel(const float* __restrict__ gsum, const int* __restrict__ gcnt,
                                  const float* __restrict__ lw, const float* __restrict__ lb,
                                  float* __restrict__ out, int G) {
    int t = blockIdx.x * blockDim.x + threadIdx.x;
    int g = t >> 5, lane = t & 31;
    if (g >= G) return;
    float2 v = ((const float2*)(gsum + (size_t)g * 64))[lane];
    int k0 = 2 * lane, k1 = 2 * lane + 1;
    float a0 = v.x * lw[k0 * 2 + 0] + v.y * lw[k1 * 2 + 0];
    float a1 = v.x * lw[k0 * 2 + 1] + v.y * lw[k1 * 2 + 1];
#pragma unroll
    for (int off = 16; off; off >>= 1) {
        a0 += __shfl_down_sync(0xffffffff, a0, off);
        a1 += __shfl_down_sync(0xffffffff, a1, off);
    }
    if (lane == 0) {
        float c = fmaxf((float)gcnt[g], 1.0f);
        out[g * 2 + 0] = a0 / c + lb[0];
        out[g * 2 + 1] = a1 / c + lb[1];
    }
}

// ---------------------------------------------------------------------------
extern "C" void kernel_launch(void* const* d_in, const int* in_sizes, int n_in,
                              void* d_out, int out_size) {
    const int*   sid   = (const int*)d_in[0];
    const int*   cid   = (const int*)d_in[1];
    const int*   pid   = (const int*)d_in[2];
    const int*   ei    = (const int*)d_in[3];   // [2, E]: row0 = src, row1 = dst
    const int*   et    = (const int*)d_in[4];
    const int*   batch = (const int*)d_in[5];
    // d_in[6] = num_graphs (scalar), unused
    const float* se = (const float*)d_in[7];
    const float* ce = (const float*)d_in[8];
    const float* pe = (const float*)d_in[9];
    const float* W1 = (const float*)d_in[10];
    const float* r1 = (const float*)d_in[11];
    const float* b1 = (const float*)d_in[12];
    const float* W2 = (const float*)d_in[13];
    const float* r2 = (const float*)d_in[14];
    const float* b2 = (const float*)d_in[15];
    const float* lw = (const float*)d_in[16];
    const float* lb = (const float*)d_in[17];
    float* out = (float*)d_out;

    const int N = in_sizes[0];
    const int E = in_sizes[4];
    const int G = out_size / 2;

    void *p_x0, *p_h1, *p_h2, *p_agg, *p_cnt, *p_inv, *p_gsum, *p_gcnt;
    cudaGetSymbolAddress(&p_x0, g_x0);
    cudaGetSymbolAddress(&p_h1, g_h1);
    cudaGetSymbolAddress(&p_h2, g_h2);
    cudaGetSymbolAddress(&p_agg, g_agg);
    cudaGetSymbolAddress(&p_cnt, g_cnt);
    cudaGetSymbolAddress(&p_inv, g_inv);
    cudaGetSymbolAddress(&p_gsum, g_gsum);
    cudaGetSymbolAddress(&p_gcnt, g_gcnt);

    // smem: layer1 = 128*64*4 + 128*68*4 = 67584 B ; layer2 = 256*64*4 + 128*68*4 = 100352 B
    cudaFuncSetAttribute(transform_kernel<32, true>,
                         cudaFuncAttributeMaxDynamicSharedMemorySize, 70 * 1024);
    cudaFuncSetAttribute(transform_kernel<64, true>,
                         cudaFuncAttributeMaxDynamicSharedMemorySize, 102 * 1024);

    cudaMemsetAsync(p_cnt, 0, (size_t)N * 3 * sizeof(int));
    cudaMemsetAsync(p_gsum, 0, (size_t)G * 64 * sizeof(float));
    cudaMemsetAsync(p_gcnt, 0, (size_t)G * sizeof(int));

    count_kernel<<<(E + 255) / 256, 256>>>(ei, et, (int*)p_cnt, E);
    inv_kernel<<<(N * 3 + 255) / 256, 256>>>((const int*)p_cnt, (float*)p_inv, N * 3);
    features_kernel<<<(N * 8 + 255) / 256, 256>>>(sid, cid, pid, se, ce, pe, (float*)p_x0, N);

    // ---- Layer 1 (D = 32) ----
    cudaMemsetAsync(p_agg, 0, (size_t)N * 3 * 32 * sizeof(float));
    edge_agg_kernel<32><<<(E * 8 + 255) / 256, 256>>>(
        (const float*)p_x0, ei, et, (const float*)p_inv, (float*)p_agg, E);
    {
        int smem1 = (128 * 64 + 128 * 68) * (int)sizeof(float);  // 67584 B -> 3 blocks/SM
        transform_kernel<32, true><<<444, 256, smem1>>>(
            (const float*)p_agg, (const float*)p_x0, W1, r1, b1, (float*)p_h1, N);
    }

    // ---- Layer 2 (D = 64) ----
    cudaMemsetAsync(p_agg, 0, (size_t)N * 3 * 64 * sizeof(float));
    edge_agg_kernel<64><<<(E * 16 + 255) / 256, 256>>>(
        (const float*)p_h1, ei, et, (const float*)p_inv, (float*)p_agg, E);
    {
        int smem2 = (256 * 64 + 128 * 68) * (int)sizeof(float);  // 100352 B -> 2 blocks/SM
        transform_kernel<64, true><<<296, 256, smem2>>>(
            (const float*)p_agg, (const float*)p_h1, W2, r2, b2, (float*)p_h2, N);
    }

    // ---- Pool + head ----
    pool_kernel<<<(N * 16 + 255) / 256, 256>>>(
        (const float*)p_h2, batch, (float*)p_gsum, (int*)p_gcnt, N);
    pool_final_kernel<<<(G * 32 + 255) / 256, 256>>>(
        (const float*)p_gsum, (const int*)p_gcnt, lw, lb, out, G);
}

// round 7
// speedup vs baseline: 1.9642x; 1.1338x over previous
#include <cuda_runtime.h>
#include <cstdint>

// Problem constants (shapes are fixed by the dataset).
static constexpr int cN = 300000;
static constexpr int cE = 1500000;
static constexpr int cG = 30000;

// Scratch (device globals — no allocation allowed). Zero-initialized at load;
// the transform kernels re-zero agg1/agg2 each call to keep the invariant.
__device__ float g_x0[(size_t)cN * 32];
__device__ float g_h1[(size_t)cN * 64];
__device__ float g_h2[(size_t)cN * 64];
__device__ float g_agg1[(size_t)cN * 3 * 32];   // layer-1 aggregates [N][3][32]
__device__ float g_agg2[(size_t)cN * 3 * 64];   // layer-2 aggregates [N][3][64]
__device__ int   g_cnt[(size_t)cN * 3];
__device__ float g_inv[(size_t)cN * 3];
__device__ float g_gsum[(size_t)cG * 64];
__device__ int   g_gcnt[cG];

// ---------------------------------------------------------------------------
// Packed fp32x2 helpers (Blackwell FFMA2 path — only reachable via PTX).
__device__ __forceinline__ unsigned long long pack2(float x, float y) {
    unsigned long long r;
    asm("mov.b64 %0, {%1, %2};" : "=l"(r)
        : "r"(__float_as_uint(x)), "r"(__float_as_uint(y)));
    return r;
}
__device__ __forceinline__ void ffma2(unsigned long long& d,
                                      unsigned long long a, unsigned long long b) {
    asm("fma.rn.f32x2 %0, %1, %2, %0;" : "+l"(d) : "l"(a), "l"(b));
}
__device__ __forceinline__ void unpack2(unsigned long long v, float& lo, float& hi) {
    unsigned int a, b;
    asm("mov.b64 {%0, %1}, %2;" : "=r"(a), "=r"(b) : "l"(v));
    lo = __uint_as_float(a);
    hi = __uint_as_float(b);
}

// ---------------------------------------------------------------------------
// Per-(dst, relation) in-degree counts.
__global__ void count_kernel(const int* __restrict__ ei, const int* __restrict__ et,
                             int* __restrict__ cnt, int E) {
    int e = blockIdx.x * blockDim.x + threadIdx.x;
    if (e >= E) return;
    atomicAdd(&cnt[ei[E + e] * 3 + et[e]], 1);
}

// inv[i] = 1 / max(cnt[i], 1)
__global__ void inv_kernel(const int* __restrict__ cnt, float* __restrict__ inv, int M) {
    int i = blockIdx.x * blockDim.x + threadIdx.x;
    if (i >= M) return;
    inv[i] = __fdividef(1.0f, (float)max(cnt[i], 1));
}

// Node features: x0 = shape_emb[sid] + col_emb[cid] + pos_emb[pid]  (N x 32)
__global__ void features_kernel(const int* __restrict__ sid, const int* __restrict__ cid,
                                const int* __restrict__ pid,
                                const float* __restrict__ se, const float* __restrict__ ce,
                                const float* __restrict__ pe,
                                float* __restrict__ x0, int N) {
    int t = blockIdx.x * blockDim.x + threadIdx.x;
    int n = t >> 3, q = t & 7;
    if (n >= N) return;
    float4 a = ((const float4*)(se + (size_t)sid[n] * 32))[q];
    float4 b = ((const float4*)(ce + (size_t)cid[n] * 32))[q];
    float4 c = ((const float4*)(pe + (size_t)pid[n] * 32))[q];
    ((float4*)(x0 + (size_t)n * 32))[q] =
        make_float4(a.x + b.x + c.x, a.y + b.y + c.y, a.z + b.z + c.z, a.w + b.w + c.w);
}

// Edge aggregation: agg[dst][et][*] += x[src][*] * inv[dst][et]
// D/4 lanes per edge; one vector RED (red.global.add.v4.f32) per lane.
template <int D>
__global__ void edge_agg_kernel(const float* __restrict__ xin,
                                const int* __restrict__ ei,
                                const int* __restrict__ et,
                                const float* __restrict__ inv,
                                float* __restrict__ agg, int E) {
    constexpr int L = D / 4;
    int t = blockIdx.x * blockDim.x + threadIdx.x;
    int e = t / L, q = t % L;
    if (e >= E) return;
    int s = ei[e], d = ei[E + e], r = et[e];
    int slot = d * 3 + r;
    float w = inv[slot];
    float4 v = ((const float4*)(xin + (size_t)s * D))[q];
    float* o = agg + (size_t)slot * D + q * 4;
    asm volatile("red.global.add.v4.f32 [%0], {%1, %2, %3, %4};"
                 :: "l"(o), "f"(v.x * w), "f"(v.y * w), "f"(v.z * w), "f"(v.w * w)
                 : "memory");
}

// Fused transform: out[n] = act( b + agg[n] (3D wide) @ vstack(W_r) + x[n] @ root )
// = one logical [N x 4D] @ [4D x 64] GEMM, run on the packed-fp32 (FFMA2) pipe.
// Block = 256 threads; tile = 128 nodes. Thread = (group g: 8 nodes) x (lane: 4 outs).
// Inputs staged k-major in smem so node-pairs are contiguous -> LDS.64 feeds
// fma.rn.f32x2 with {node 2p, node 2p+1}; weights duplicated into both halves.
// Per k per warp: 1 LDS.128 + 4 LDS.64 + 4 packs + 16 FFMA2  (FMA-pipe bound).
// Also zeroes `zbuf` (the OTHER layer's agg buffer) for the next use — the
// zero-store DRAM traffic hides under the FMA-bound mainloop.
template <int D, bool RELU>
__global__ void __launch_bounds__(256)
transform_kernel(const float* __restrict__ agg,
                 const float* __restrict__ xin,
                 const float* __restrict__ W,     // [3*D][64]
                 const float* __restrict__ root,  // [D][64]
                 const float* __restrict__ bias,  // [64]
                 float* __restrict__ out,
                 float* __restrict__ zbuf, int zf4,  // float4s per node to zero
                 int N) {
    constexpr int IN = 4 * D;          // 128 / 256
    constexpr int CH = 64;             // k-chunk staged per pass
    constexpr int NCH = IN / CH;       // 2 / 4
    constexpr int TS = 132;            // k-major row stride (128 nodes + pad)
    extern __shared__ float smem[];
    float4* Ws = (float4*)smem;              // [IN*16]: Ws[k*16+l] = W[k][4l..4l+3]
    float*  ins = smem + (size_t)IN * 64;    // [CH][TS], k-major

    for (int i = threadIdx.x; i < IN * 16; i += 256) {
        int k = i >> 4, l = i & 15;
        const float* row = (k < 3 * D) ? (W + (size_t)k * 64) : (root + (size_t)(k - 3 * D) * 64);
        Ws[i] = ((const float4*)row)[l];
    }

    int lane = threadIdx.x & 15;   // output quad
    int g    = threadIdx.x >> 4;   // node group (8 nodes = 4 pairs)
    float4 b4 = ((const float4*)bias)[lane];
    unsigned long long binit[4] = {pack2(b4.x, b4.x), pack2(b4.y, b4.y),
                                   pack2(b4.z, b4.z), pack2(b4.w, b4.w)};

    for (int tile = blockIdx.x * 128; tile < N; tile += gridDim.x * 128) {
        unsigned long long acc[4][4];  // [node pair][output component]
#pragma unroll
        for (int p = 0; p < 4; p++)
#pragma unroll
            for (int o = 0; o < 4; o++) acc[p][o] = binit[o];

#pragma unroll
        for (int c = 0; c < NCH; c++) {
            __syncthreads();   // covers initial weight load / previous chunk reads
            // Stage chunk c transposed: ins[k - c*CH][node]. Unit i = (kq, n).
            for (int i = threadIdx.x; i < 128 * 16; i += 256) {
                int n = i & 127, kq = i >> 7;          // kq in [0,16) -> 4 k's each
                int node = tile + n;
                float4 v = make_float4(0.f, 0.f, 0.f, 0.f);
                int gq = c * 16 + kq;                  // float4 index within node row
                if (node < N) {
                    if (gq < 3 * D / 4) v = ((const float4*)agg)[(size_t)node * (3 * D / 4) + gq];
                    else                v = ((const float4*)xin)[(size_t)node * (D / 4) + gq - 3 * D / 4];
                }
                float* p0 = ins + (size_t)(kq * 4) * TS + n;
                p0[0]      = v.x;
                p0[TS]     = v.y;
                p0[2 * TS] = v.z;
                p0[3 * TS] = v.w;
            }
            __syncthreads();

            const float* grow = ins + g * 8;
#pragma unroll 8
            for (int k = 0; k < CH; k++) {
                float4 w = Ws[(c * CH + k) * 16 + lane];
                unsigned long long wx = pack2(w.x, w.x);
                unsigned long long wy = pack2(w.y, w.y);
                unsigned long long wz = pack2(w.z, w.z);
                unsigned long long ww = pack2(w.w, w.w);
                const float* row = grow + (size_t)k * TS;
#pragma unroll
                for (int p = 0; p < 4; p++) {
                    unsigned long long v = *(const unsigned long long*)(row + 2 * p);
                    ffma2(acc[p][0], v, wx);
                    ffma2(acc[p][1], v, wy);
                    ffma2(acc[p][2], v, wz);
                    ffma2(acc[p][3], v, ww);
                }
            }
        }

        // Epilogue: acc[p][o].lo -> node tile+g*8+2p, .hi -> node +1.
#pragma unroll
        for (int p = 0; p < 4; p++) {
            float4 r0, r1;
            unpack2(acc[p][0], r0.x, r1.x);
            unpack2(acc[p][1], r0.y, r1.y);
            unpack2(acc[p][2], r0.z, r1.z);
            unpack2(acc[p][3], r0.w, r1.w);
            if (RELU) {
                r0.x = fmaxf(r0.x, 0.f); r0.y = fmaxf(r0.y, 0.f);
                r0.z = fmaxf(r0.z, 0.f); r0.w = fmaxf(r0.w, 0.f);
                r1.x = fmaxf(r1.x, 0.f); r1.y = fmaxf(r1.y, 0.f);
                r1.z = fmaxf(r1.z, 0.f); r1.w = fmaxf(r1.w, 0.f);
            }
            int n0 = tile + g * 8 + 2 * p;
            if (n0 < N)     ((float4*)(out + (size_t)n0 * 64))[lane] = r0;
            if (n0 + 1 < N) ((float4*)(out + (size_t)(n0 + 1) * 64))[lane] = r1;
        }

        // Zero-fold: clear the other layer's agg buffer for this node tile.
        {
            const float4 z4 = make_float4(0.f, 0.f, 0.f, 0.f);
            size_t lim = (size_t)N * zf4;
            for (int i = threadIdx.x; i < 128 * zf4; i += 256) {
                size_t idx = (size_t)tile * zf4 + i;
                if (idx < lim) ((float4*)zbuf)[idx] = z4;
            }
        }
    }
}

// Global mean pool (sum + count); 16 lanes per node, vector RED.
__global__ void pool_kernel(const float* __restrict__ h, const int* __restrict__ batch,
                            float* __restrict__ gsum, int* __restrict__ gcnt, int N) {
    int t = blockIdx.x * blockDim.x + threadIdx.x;
    int n = t >> 4, q = t & 15;
    if (n >= N) return;
    int b = batch[n];
    float4 v = ((const float4*)(h + (size_t)n * 64))[q];
    float* o = gsum + (size_t)b * 64 + q * 4;
    asm volatile("red.global.add.v4.f32 [%0], {%1, %2, %3, %4};"
                 :: "l"(o), "f"(v.x), "f"(v.y), "f"(v.z), "f"(v.w)
                 : "memory");
    if (q == 0) atomicAdd(&gcnt[b], 1);
}

// Final: out[g] = (gsum[g]/max(cnt,1)) @ lin_W + lin_b. One warp per graph.
__global__ void pool_final_kernel(const float* __restrict__ gsum, const int* __restrict__ gcnt,
                                  const float* __restrict__ lw, const float* __restrict__ lb,
                                  float* __restrict__ out, int G) {
    int t = blockIdx.x * blockDim.x + threadIdx.x;
    int g = t >> 5, lane = t & 31;
    if (g >= G) return;
    float2 v = ((const float2*)(gsum + (size_t)g * 64))[lane];
    int k0 = 2 * lane, k1 = 2 * lane + 1;
    float a0 = v.x * lw[k0 * 2 + 0] + v.y * lw[k1 * 2 + 0];
    float a1 = v.x * lw[k0 * 2 + 1] + v.y * lw[k1 * 2 + 1];
#pragma unroll
    for (int off = 16; off; off >>= 1) {
        a0 += __shfl_down_sync(0xffffffff, a0, off);
        a1 += __shfl_down_sync(0xffffffff, a1, off);
    }
    if (lane == 0) {
        float c = fmaxf((float)gcnt[g], 1.0f);
        out[g * 2 + 0] = a0 / c + lb[0];
        out[g * 2 + 1] = a1 / c + lb[1];
    }
}

// ---------------------------------------------------------------------------
extern "C" void kernel_launch(void* const* d_in, const int* in_sizes, int n_in,
                              void* d_out, int out_size) {
    const int*   sid   = (const int*)d_in[0];
    const int*   cid   = (const int*)d_in[1];
    const int*   pid   = (const int*)d_in[2];
    const int*   ei    = (const int*)d_in[3];   // [2, E]: row0 = src, row1 = dst
    const int*   et    = (const int*)d_in[4];
    const int*   batch = (const int*)d_in[5];
    // d_in[6] = num_graphs (scalar), unused
    const float* se = (const float*)d_in[7];
    const float* ce = (const float*)d_in[8];
    const float* pe = (const float*)d_in[9];
    const float* W1 = (const float*)d_in[10];
    const float* r1 = (const float*)d_in[11];
    const float* b1 = (const float*)d_in[12];
    const float* W2 = (const float*)d_in[13];
    const float* r2 = (const float*)d_in[14];
    const float* b2 = (const float*)d_in[15];
    const float* lw = (const float*)d_in[16];
    const float* lb = (const float*)d_in[17];
    float* out = (float*)d_out;

    const int N = in_sizes[0];
    const int E = in_sizes[4];
    const int G = out_size / 2;

    void *p_x0, *p_h1, *p_h2, *p_agg1, *p_agg2, *p_cnt, *p_inv, *p_gsum, *p_gcnt;
    cudaGetSymbolAddress(&p_x0, g_x0);
    cudaGetSymbolAddress(&p_h1, g_h1);
    cudaGetSymbolAddress(&p_h2, g_h2);
    cudaGetSymbolAddress(&p_agg1, g_agg1);
    cudaGetSymbolAddress(&p_agg2, g_agg2);
    cudaGetSymbolAddress(&p_cnt, g_cnt);
    cudaGetSymbolAddress(&p_inv, g_inv);
    cudaGetSymbolAddress(&p_gsum, g_gsum);
    cudaGetSymbolAddress(&p_gcnt, g_gcnt);

    // smem: layer1 = 128*64*4 + 64*132*4 = 66560 B (3 blocks/SM)
    //       layer2 = 256*64*4 + 64*132*4 = 99328 B (2 blocks/SM)
    cudaFuncSetAttribute(transform_kernel<32, true>,
                         cudaFuncAttributeMaxDynamicSharedMemorySize, 70 * 1024);
    cudaFuncSetAttribute(transform_kernel<64, true>,
                         cudaFuncAttributeMaxDynamicSharedMemorySize, 100 * 1024);

    cudaMemsetAsync(p_cnt, 0, (size_t)N * 3 * sizeof(int));
    cudaMemsetAsync(p_gsum, 0, (size_t)G * 64 * sizeof(float));
    cudaMemsetAsync(p_gcnt, 0, (size_t)G * sizeof(int));

    count_kernel<<<(E + 255) / 256, 256>>>(ei, et, (int*)p_cnt, E);
    inv_kernel<<<(N * 3 + 255) / 256, 256>>>((const int*)p_cnt, (float*)p_inv, N * 3);
    features_kernel<<<(N * 8 + 255) / 256, 256>>>(sid, cid, pid, se, ce, pe, (float*)p_x0, N);

    // ---- Layer 1 (D = 32) ----
    // agg1 was zeroed by the previous call's transform<64> (or load-time init).
    edge_agg_kernel<32><<<(E * 8 + 255) / 256, 256>>>(
        (const float*)p_x0, ei, et, (const float*)p_inv, (float*)p_agg1, E);
    {
        int smem1 = (128 * 64 + 64 * 132) * (int)sizeof(float);  // 66560 B
        transform_kernel<32, true><<<444, 256, smem1>>>(
            (const float*)p_agg1, (const float*)p_x0, W1, r1, b1, (float*)p_h1,
            (float*)p_agg2, 3 * 64 / 4, N);   // zero agg2 for layer 2
    }

    // ---- Layer 2 (D = 64) ----
    edge_agg_kernel<64><<<(E * 16 + 255) / 256, 256>>>(
        (const float*)p_h1, ei, et, (const float*)p_inv, (float*)p_agg2, E);
    {
        int smem2 = (256 * 64 + 64 * 132) * (int)sizeof(float);  // 99328 B
        transform_kernel<64, true><<<296, 256, smem2>>>(
            (const float*)p_agg2, (const float*)p_h1, W2, r2, b2, (float*)p_h2,
            (float*)p_agg1, 3 * 32 / 4, N);   // zero agg1 for the next call
    }

    // ---- Pool + head ----
    pool_kernel<<<(N * 16 + 255) / 256, 256>>>(
        (const float*)p_h2, batch, (float*)p_gsum, (int*)p_gcnt, N);
    pool_final_kernel<<<(G * 32 + 255) / 256, 256>>>(
        (const float*)p_gsum, (const int*)p_gcnt, lw, lb, out, G);
}